// round 5
// baseline (speedup 1.0000x reference)
#include <cuda_runtime.h>
#include <cstdint>

#define BATCH    1024
#define VOCAB    100000
#define DIM      128
#define NSEG     3
#define NBINS    4096
#define HOTCAP   3072
#define NTHREADS 512
#define CUT0 100
#define CUT1 500
#define CUT2 1000
#define TGUESS 2.0f          // rank-1000 of 100k N(0,1) ~ 2.33; P(v>2)~2.3% -> ~2275 cands

__device__ float g_rh[NSEG * BATCH * DIM];
__device__ int   g_idx[BATCH * CUT2];
__device__ float g_val[BATCH * CUT2];

// ---------------------------------------------------------------------------
// Kernel 1: rerank_hidden = hidden @ W[seg]^T + b[seg], tiled smem GEMM.
// ---------------------------------------------------------------------------
#define RTILE 32
#define KC 64
__global__ void __launch_bounds__(256)
rh_kernel(const float* __restrict__ hidden,
          const float* __restrict__ W,
          const float* __restrict__ bias)
{
    __shared__ float Wt[DIM][KC + 1];
    __shared__ float hs[RTILE][KC];
    const int seg = blockIdx.y;
    const int r0  = blockIdx.x * RTILE;
    const int t   = threadIdx.x;
    const int d   = t & 127;
    const int rhh = t >> 7;

    float acc[16];
#pragma unroll
    for (int i = 0; i < 16; i++) acc[i] = 0.f;

    const float* Wseg = W + (size_t)seg * DIM * DIM;

    for (int kc = 0; kc < DIM; kc += KC) {
        __syncthreads();
#pragma unroll
        for (int j = 0; j < 32; j++) {
            int e = t + j * 256;
            int dd = e >> 6, kk = e & 63;
            Wt[dd][kk] = Wseg[dd * DIM + kc + kk];
        }
#pragma unroll
        for (int j = 0; j < 8; j++) {
            int e = t + j * 256;
            int rr = e >> 6, kk = e & 63;
            hs[rr][kk] = hidden[(size_t)(r0 + rr) * DIM + kc + kk];
        }
        __syncthreads();
#pragma unroll 8
        for (int k = 0; k < KC; k++) {
            float wv = Wt[d][k];
#pragma unroll
            for (int r = 0; r < 16; r++)
                acc[r] += hs[rhh * 16 + r][k] * wv;
        }
    }
    float bv = bias[seg * DIM + d];
#pragma unroll
    for (int r = 0; r < 16; r++) {
        int row = r0 + rhh * 16 + r;
        g_rh[(size_t)seg * BATCH * DIM + (size_t)row * DIM + d] = acc[r] + bv;
    }
}

__device__ __forceinline__ unsigned mono(float f) {
    unsigned u = __float_as_uint(f);
    return (u & 0x80000000u) ? ~u : (u | 0x80000000u);
}

// ---------------------------------------------------------------------------
// Scan 4096-bin histogram in descending-value order with shfl (2 barriers).
// ---------------------------------------------------------------------------
__device__ void scan_find(unsigned* hist, unsigned* warpsum, int tid,
                          int* s_bin, int* s_rank)
{
    const int lane = tid & 31, w = tid >> 5;
    unsigned c[8];
    unsigned chunk = 0;
#pragma unroll
    for (int j = 0; j < 8; j++) {
        c[j] = hist[4095 - 8 * tid - j];
        chunk += c[j];
    }
    unsigned pfx = chunk;
#pragma unroll
    for (int off = 1; off < 32; off <<= 1) {
        unsigned n = __shfl_up_sync(0xFFFFFFFFu, pfx, off);
        if (lane >= off) pfx += n;
    }
    if (lane == 31) warpsum[w] = pfx;
    __syncthreads();
    if (w == 0) {
        unsigned s = (lane < 16) ? warpsum[lane] : 0u;
#pragma unroll
        for (int off = 1; off < 16; off <<= 1) {
            unsigned n = __shfl_up_sync(0xFFFFFFFFu, s, off);
            if (lane >= off) s += n;
        }
        if (lane < 16) warpsum[lane] = s;
    }
    __syncthreads();
    unsigned wbase = (w > 0) ? warpsum[w - 1] : 0u;
    unsigned incl = wbase + pfx;
    unsigned excl = incl - chunk;
    const unsigned Ks[3] = {CUT0, CUT1, CUT2};
#pragma unroll
    for (int kk = 0; kk < 3; kk++) {
        unsigned K = Ks[kk];
        if (excl < K && K <= incl) {
            unsigned cc = excl;
#pragma unroll
            for (int j = 0; j < 8; j++) {
                unsigned h = c[j];
                if (cc < K && K <= cc + h) {
                    s_bin[kk]  = 4095 - 8 * tid - j;
                    s_rank[kk] = (int)(K - cc);
                    break;
                }
                cc += h;
            }
        }
    }
    __syncthreads();
}

// ---------------------------------------------------------------------------
// Kernel 2: READ-ONLY collect + select + dot. Results go to scratch.
// ---------------------------------------------------------------------------
__global__ void __launch_bounds__(NTHREADS, 3)
collect_kernel(const float* __restrict__ logits,
               const float* __restrict__ emb)
{
    __shared__ unsigned long long hot[HOTCAP];
    __shared__ unsigned hist[NBINS];
    __shared__ unsigned warpsum[16];
    __shared__ float rh[NSEG * DIM];
    __shared__ unsigned long long Tkey[3];
    __shared__ int s_bin[3];
    __shared__ int s_rank[3];
    __shared__ int s_nhot;
    __shared__ int s_dcnt;

    const int row = blockIdx.x;
    const int tid = threadIdx.x;
    const int lane = tid & 31;
    const unsigned BASE = 0xC0000000u;           // mono(2.0f)

    for (int i = tid; i < NBINS; i += NTHREADS) hist[i] = 0u;
    if (tid < NSEG * DIM) {
        int seg = tid >> 7, d = tid & 127;
        rh[tid] = g_rh[(size_t)seg * BATCH * DIM + (size_t)row * DIM + d];
    }
    if (tid == 0) { s_nhot = 0; s_dcnt = 0; }
    __syncthreads();

    const float4* row4 = (const float4*)(logits + (size_t)row * VOCAB);
    const int NV4  = VOCAB / 4;                  // 25000
    const int MAIN = (NV4 / (NTHREADS * 4)) * (NTHREADS * 4);   // 24576

    // ------- Pass 1: read-only 4-way batched scan, warp-aggregated push -----
    for (int base = 0; base < MAIN; base += NTHREADS * 4) {
        const int i0 = base + tid;
        float4 v0 = __ldcs(&row4[i0]);
        float4 v1 = __ldcs(&row4[i0 +     NTHREADS]);
        float4 v2 = __ldcs(&row4[i0 + 2 * NTHREADS]);
        float4 v3 = __ldcs(&row4[i0 + 3 * NTHREADS]);

        unsigned msk = 0;
        msk |= (v0.x > TGUESS) << 0;  msk |= (v0.y > TGUESS) << 1;
        msk |= (v0.z > TGUESS) << 2;  msk |= (v0.w > TGUESS) << 3;
        msk |= (v1.x > TGUESS) << 4;  msk |= (v1.y > TGUESS) << 5;
        msk |= (v1.z > TGUESS) << 6;  msk |= (v1.w > TGUESS) << 7;
        msk |= (v2.x > TGUESS) << 8;  msk |= (v2.y > TGUESS) << 9;
        msk |= (v2.z > TGUESS) << 10; msk |= (v2.w > TGUESS) << 11;
        msk |= (v3.x > TGUESS) << 12; msk |= (v3.y > TGUESS) << 13;
        msk |= (v3.z > TGUESS) << 14; msk |= (v3.w > TGUESS) << 15;
        int cnt = __popc(msk);

        if (__ballot_sync(0xFFFFFFFFu, cnt > 0)) {
            int pfx = cnt;
#pragma unroll
            for (int off = 1; off < 32; off <<= 1) {
                int n = __shfl_up_sync(0xFFFFFFFFu, pfx, off);
                if (lane >= off) pfx += n;
            }
            int total = __shfl_sync(0xFFFFFFFFu, pfx, 31);
            int wbase = 0;
            if (lane == 31) wbase = atomicAdd(&s_nhot, total);
            wbase = __shfl_sync(0xFFFFFFFFu, wbase, 31);
            int slot = wbase + pfx - cnt;
            if (cnt) {
                const float4 vv[4] = {v0, v1, v2, v3};
#pragma unroll
                for (int j = 0; j < 4; j++) {
                    if ((msk >> (4 * j)) & 0xF) {
                        int gi = 4 * (i0 + j * NTHREADS);
                        float c4[4] = {vv[j].x, vv[j].y, vv[j].z, vv[j].w};
#pragma unroll
                        for (int q = 0; q < 4; q++) {
                            if ((msk >> (4 * j + q)) & 1) {
                                unsigned m = mono(c4[q]);
                                if (slot < HOTCAP) {
                                    hot[slot] = ((unsigned long long)m << 32)
                                              | (unsigned)(~(gi + q));
                                    unsigned fb = (m - BASE) >> 12;
                                    if (fb > 4095u) fb = 4095u;
                                    atomicAdd(&hist[fb], 1u);
                                }
                                slot++;
                            }
                        }
                    }
                }
            }
        }
    }
    // tail: 424 float4s
    {
        int i0 = MAIN + tid;
        if (i0 < NV4) {
            float4 v = __ldcs(&row4[i0]);
            unsigned msk = 0;
            msk |= (v.x > TGUESS) << 0; msk |= (v.y > TGUESS) << 1;
            msk |= (v.z > TGUESS) << 2; msk |= (v.w > TGUESS) << 3;
            int cnt = __popc(msk);
            if (__ballot_sync(__activemask(), cnt > 0)) {
                if (cnt) {
                    int slot = atomicAdd(&s_nhot, cnt);
                    float c4[4] = {v.x, v.y, v.z, v.w};
#pragma unroll
                    for (int q = 0; q < 4; q++) {
                        if ((msk >> q) & 1) {
                            unsigned m = mono(c4[q]);
                            if (slot < HOTCAP) {
                                hot[slot] = ((unsigned long long)m << 32)
                                          | (unsigned)(~(4 * i0 + q));
                                unsigned fb = (m - BASE) >> 12;
                                if (fb > 4095u) fb = 4095u;
                                atomicAdd(&hist[fb], 1u);
                            }
                            slot++;
                        }
                    }
                }
            }
        }
    }
    __syncthreads();

    int nhot = s_nhot;
    bool fast = (nhot >= CUT2) && (nhot <= HOTCAP);

    if (fast) {
        scan_find(hist, warpsum, tid, s_bin, s_rank);
        const int b0 = s_bin[0], b1 = s_bin[1], b2 = s_bin[2];
        for (int i = tid; i < nhot; i += NTHREADS) {
            unsigned long long k = hot[i];
            unsigned fb = ((unsigned)(k >> 32) - BASE) >> 12;
            if (fb > 4095u) fb = 4095u;
            int bin = (int)fb;
            bool m0 = (bin == b0), m1 = (bin == b1), m2 = (bin == b2);
            if (m0 | m1 | m2) {
                int cnt = 0;
                for (int j = 0; j < nhot; j++) {
                    unsigned long long kj = hot[j];
                    unsigned fbj = ((unsigned)(kj >> 32) - BASE) >> 12;
                    if (fbj > 4095u) fbj = 4095u;
                    if ((int)fbj == bin && kj > k) cnt++;
                }
                int r = cnt + 1;
                if (m0 && r == s_rank[0]) Tkey[0] = k;
                if (m1 && r == s_rank[1]) Tkey[1] = k;
                if (m2 && r == s_rank[2]) Tkey[2] = k;
            }
        }
        __syncthreads();
    } else {
        // ------- Fallback: full coarse histogram over the row -------
        for (int i = tid; i < NBINS; i += NTHREADS) hist[i] = 0u;
        if (tid == 0) s_nhot = 0;
        __syncthreads();
        for (int i = tid; i < NV4; i += NTHREADS) {
            float4 v = row4[i];
            atomicAdd(&hist[mono(v.x) >> 20], 1u);
            atomicAdd(&hist[mono(v.y) >> 20], 1u);
            atomicAdd(&hist[mono(v.z) >> 20], 1u);
            atomicAdd(&hist[mono(v.w) >> 20], 1u);
        }
        __syncthreads();
        scan_find(hist, warpsum, tid, s_bin, s_rank);
        const int cb2 = s_bin[2];
        for (int i = tid; i < NV4; i += NTHREADS) {
            float4 v = row4[i];
            float vals[4] = {v.x, v.y, v.z, v.w};
            int b4 = 4 * i;
#pragma unroll
            for (int j = 0; j < 4; j++) {
                unsigned m = mono(vals[j]);
                if ((int)(m >> 20) >= cb2) {
                    int p = atomicAdd(&s_nhot, 1);
                    if (p < HOTCAP)
                        hot[p] = ((unsigned long long)m << 32) | (unsigned)(~(b4 + j));
                }
            }
        }
        __syncthreads();
        nhot = (s_nhot < HOTCAP) ? s_nhot : HOTCAP;
        const int b0 = s_bin[0], b1 = s_bin[1], b2 = s_bin[2];
        for (int i = tid; i < nhot; i += NTHREADS) {
            unsigned long long k = hot[i];
            int bin = (int)(k >> 52);
            bool m0 = (bin == b0), m1 = (bin == b1), m2 = (bin == b2);
            if (m0 | m1 | m2) {
                int cnt = 0;
                for (int j = 0; j < nhot; j++) {
                    unsigned long long kj = hot[j];
                    if ((int)(kj >> 52) == bin && kj > k) cnt++;
                }
                int r = cnt + 1;
                if (m0 && r == s_rank[0]) Tkey[0] = k;
                if (m1 && r == s_rank[1]) Tkey[1] = k;
                if (m2 && r == s_rank[2]) Tkey[2] = k;
            }
        }
        __syncthreads();
    }

    const unsigned long long T0 = Tkey[0], T1 = Tkey[1], T2 = Tkey[2];

    // ------- Dot phase: warp per candidate; exactly CUT2 survivors ----------
    const int wid = tid >> 5;
    const int NW = NTHREADS / 32;
    const float4* emb4 = (const float4*)emb;
    const float4* rh4  = (const float4*)rh;
    int*   oidx = g_idx + (size_t)row * CUT2;
    float* oval = g_val + (size_t)row * CUT2;

    for (int s = wid * 2; s < nhot; s += NW * 2) {
        unsigned long long k[2];
        bool act[2];
        unsigned idx[2];
        float4 e[2];
        int seg[2];
#pragma unroll
        for (int j = 0; j < 2; j++) {
            int si = s + j;
            k[j] = (si < nhot) ? hot[si] : 0ull;
            act[j] = (k[j] >= T2);
            if (act[j]) {
                seg[j] = (k[j] >= T0) ? 0 : ((k[j] >= T1) ? 1 : 2);
                idx[j] = ~(unsigned)k[j];
                e[j] = emb4[(size_t)idx[j] * (DIM / 4) + lane];
            }
        }
#pragma unroll
        for (int j = 0; j < 2; j++) {
            if (!act[j]) continue;
            float4 r = rh4[seg[j] * (DIM / 4) + lane];
            float p = e[j].x * r.x + e[j].y * r.y + e[j].z * r.z + e[j].w * r.w;
            p += __shfl_xor_sync(0xFFFFFFFFu, p, 16);
            p += __shfl_xor_sync(0xFFFFFFFFu, p, 8);
            p += __shfl_xor_sync(0xFFFFFFFFu, p, 4);
            p += __shfl_xor_sync(0xFFFFFFFFu, p, 2);
            p += __shfl_xor_sync(0xFFFFFFFFu, p, 1);
            if (lane == 0) {
                int slot = atomicAdd(&s_dcnt, 1);
                if (slot < CUT2) { oidx[slot] = (int)idx[j]; oval[slot] = p; }
            }
        }
    }
}

// ---------------------------------------------------------------------------
// Kernel 3: scatter the CUT2 rerank results into the copied output.
// ---------------------------------------------------------------------------
__global__ void __launch_bounds__(256)
scatter_kernel(float* __restrict__ out)
{
    const int row = blockIdx.x;
    const int*   oidx = g_idx + (size_t)row * CUT2;
    const float* oval = g_val + (size_t)row * CUT2;
    float* outrow = out + (size_t)row * VOCAB;
    for (int s = threadIdx.x; s < CUT2; s += 256) {
        outrow[oidx[s]] = oval[s];
    }
}

extern "C" void kernel_launch(void* const* d_in, const int* in_sizes, int n_in,
                              void* d_out, int out_size)
{
    const float* hidden = nullptr;
    const float* logits = nullptr;
    const float* emb    = nullptr;
    const float* W      = nullptr;
    const float* bias   = nullptr;
    for (int i = 0; i < n_in; i++) {
        switch (in_sizes[i]) {
            case BATCH * DIM:      hidden = (const float*)d_in[i]; break;
            case BATCH * VOCAB:    logits = (const float*)d_in[i]; break;
            case VOCAB * DIM:      emb    = (const float*)d_in[i]; break;
            case NSEG * DIM * DIM: W      = (const float*)d_in[i]; break;
            case NSEG * DIM:       bias   = (const float*)d_in[i]; break;
        }
    }
    float* out = (float*)d_out;

    rh_kernel<<<dim3(BATCH / RTILE, NSEG), 256>>>(hidden, W, bias);
    collect_kernel<<<BATCH, NTHREADS>>>(logits, emb);
    cudaMemcpyAsync(out, logits, (size_t)BATCH * VOCAB * sizeof(float),
                    cudaMemcpyDeviceToDevice, 0);
    scatter_kernel<<<BATCH, 256>>>(out);
}